// round 15
// baseline (speedup 1.0000x reference)
#include <cuda_runtime.h>

#define BB 32
#define SS 256
#define EE 256
#define HH 8
#define DKK 32
#define LL 4
#define TT (BB*SS)
#define E3 (3*EE)
#define QKVW 2304
#define XHW 1024

__device__ float g_xh[TT*XHW];
__device__ float g_qkv[TT*QKVW];
__device__ float g_h[TT*EE];
__device__ float g_h2[TT*EE];
__device__ float g_wqkvT[LL*QKVW*EE];   // [l][c][e]
__device__ float g_wfT[12*EE*EE];       // [z][n][j]
__device__ float g_wffT[LL*EE*EE];      // [l][n][k]
__device__ float g_woR[12*EE*EE];
__device__ float g_wcomb[12*EE*EE];
__device__ float g_wbigT[LL*EE*XHW];    // [l][n][r]
__device__ int   g_flag[TT];
__device__ int   g_len[BB];
__device__ float g_sums[4*EE];

__device__ __forceinline__ unsigned f2tf(float x) {
    unsigned r; asm("cvt.rna.tf32.f32 %0, %1;" : "=r"(r) : "f"(x)); return r;
}
__device__ __forceinline__ float rtf(float x) { return __uint_as_float(f2tf(x)); }

#define N_PACK (12*HH*EE*DKK)
__global__ void prep_w(const float* __restrict__ Wq, const float* __restrict__ Wk,
                       const float* __restrict__ Wv, const float* __restrict__ Wo,
                       const float* __restrict__ Wf, const float* __restrict__ Wff) {
    int id = blockIdx.x*blockDim.x + threadIdx.x;
    if (id < N_PACK) {
        int d  = id % DKK;
        int e  = (id / DKK) % EE;
        int h  = (id / (DKK*EE)) % HH;
        int lg = id / (DKK*EE*HH);
        int l = lg / 3, g = lg % 3;
        int col = g*768 + h*DKK + d;
        size_t base = (size_t)l*QKVW*EE;
        g_wqkvT[base + (size_t)(col +   0)*EE + e] = rtf(Wq[id]);
        g_wqkvT[base + (size_t)(col + 256)*EE + e] = rtf(Wk[id]);
        g_wqkvT[base + (size_t)(col + 512)*EE + e] = rtf(Wv[id]);
    } else if (id < 2*N_PACK) {
        int i = id - N_PACK;
        g_woR[i] = rtf(Wo[i]);
    } else if (id < 3*N_PACK) {
        int i = id - 2*N_PACK;
        int j = i % EE, n = (i/EE) % EE, z = i/(EE*EE);
        int l = z/3, g = z%3;
        g_wfT[i] = rtf(Wf[(size_t)l*E3*EE + (size_t)(g*256+j)*EE + n]);
    } else {
        int i = id - 3*N_PACK;
        int k = i % EE, n = (i/EE) % EE, l = i/(EE*EE);
        g_wffT[i] = rtf(Wff[(size_t)l*EE*EE + (size_t)k*EE + n]);
    }
}
__global__ void assemble_wbigT(const float* __restrict__ Wf) {
    int id = blockIdx.x*blockDim.x + threadIdx.x;
    int r = id % XHW, n = (id/XHW) % EE, l = id/(XHW*EE);
    float v;
    if (r < 256) {
        const float* wf = Wf + (size_t)l*E3*EE;
        v = wf[(size_t)r*EE+n] + wf[(size_t)(256+r)*EE+n] + wf[(size_t)(512+r)*EE+n];
    } else {
        int g = (r-256) >> 8, d = (r-256) & 255;
        v = g_wcomb[(size_t)(l*3+g)*EE*EE + (size_t)d*EE + n];
    }
    g_wbigT[id] = rtf(v);
}

__global__ void flags_kernel(const float* __restrict__ data, const float* __restrict__ mask) {
    int b = blockIdx.x, s = threadIdx.x;
    int idx = b*SS + s;
    float mk = mask[idx];
    float p1 = data[idx*5+2], p2 = data[idx*5+3], p3 = data[idx*5+4];
    int f = 0;
    if (p1 == 1.0f) f = 100;
    if (p2 == 1.0f || p3 == 1.0f) f = 101;
    if (mk == 0.0f) f = 102;
    g_flag[idx] = f;
    __shared__ float red[SS];
    red[s] = mk;
    __syncthreads();
    for (int st = 128; st > 0; st >>= 1) {
        if (s < st) red[s] += red[s+st];
        __syncthreads();
    }
    if (s == 0) g_len[b] = (int)(red[0] + 0.5f);
}

__global__ void embed_kernel(const float* __restrict__ data, const float* __restrict__ Wc,
                             const float* __restrict__ bc, const float* __restrict__ ftab,
                             const float* __restrict__ ptab) {
    int t = blockIdx.x, e = threadIdx.x;
    float c0 = data[t*5+0], c1 = data[t*5+1];
    int fl = g_flag[t];
    int s = t & (SS-1);
    g_xh[(size_t)t*XHW + e] = rtf(c0*Wc[e] + c1*Wc[EE+e] + bc[e] + ftab[fl*EE+e] + ptab[s*EE+e]);
}

// ---- tf32 mma.sync GEMM: tile 128(M)x64(N), 8 warps (warp-tile 32x32), 3 CTAs/SM --
__device__ __forceinline__ void cpasync16(float* dst, const float* src) {
    unsigned s = (unsigned)__cvta_generic_to_shared(dst);
    asm volatile("cp.async.cg.shared.global [%0], [%1], 16;" :: "r"(s), "l"(src));
}
#define TILE_ST 36
#define TILE_A_W (128*TILE_ST)          // 4608 words
#define TILE_B_W (64*TILE_ST)           // 2304 words
#define BUF_W (TILE_A_W + TILE_B_W)     // 6912 words
#define GEMM_SMEM (2*BUF_W*4)           // 55296 B; 3 CTAs/SM = 166 KB

__device__ __forceinline__ void load_tile(float* bufA, float* bufB,
        const float* A, const float* BT, int lda, int ldb,
        int m0, int n0, int k0, int tid)
{
    {   // A: 128 rows x 32 k; thread -> 16 floats of one row
        int row = tid >> 1, c = (tid & 1)*16;
        const float* src = A + (size_t)(m0 + row)*lda + k0 + c;
        float* dst = bufA + row*TILE_ST + c;
        cpasync16(dst, src);       cpasync16(dst + 4,  src + 4);
        cpasync16(dst + 8, src+8); cpasync16(dst + 12, src + 12);
    }
    {   // B: 64 rows x 32 k; thread -> 8 floats of one row
        int row = tid >> 2, c = (tid & 3)*8;
        const float* src = BT + (size_t)(n0 + row)*ldb + k0 + c;
        float* dst = bufB + row*TILE_ST + c;
        cpasync16(dst, src);       cpasync16(dst + 4, src + 4);
    }
    asm volatile("cp.async.commit_group;");
}

__global__ void __launch_bounds__(256, 3) mma_gemm(
    const float* __restrict__ A, const float* __restrict__ BT, float* __restrict__ C,
    int K, int lda, int ldb, int ldc,
    const float* __restrict__ bias, const float* __restrict__ resid, int ldr, int relu,
    size_t batchA, size_t batchB, size_t batchC, float* stats)
{
    extern __shared__ float smem[];
    int z = blockIdx.z;
    A  += (size_t)z*batchA; BT += (size_t)z*batchB; C += (size_t)z*batchC;
    int tid = threadIdx.x, lane = tid & 31, warp = tid >> 5;
    int wm = warp & 3, wn = warp >> 2;     // warp tile 32(M) x 32(N)
    int m0 = blockIdx.y*128, n0 = blockIdx.x*64;
    float acc[2][4][4];
#pragma unroll
    for (int a2 = 0; a2 < 2; a2++)
#pragma unroll
        for (int b2 = 0; b2 < 4; b2++)
#pragma unroll
            for (int c2 = 0; c2 < 4; c2++) acc[a2][b2][c2] = 0.0f;

    unsigned sbase = (unsigned)__cvta_generic_to_shared(smem);
    unsigned aoff = ((unsigned)((wm*32 + (lane & 15))*TILE_ST) + (lane >= 16 ? 4u : 0u))*4u;
    unsigned boff = (unsigned)TILE_A_W*4u +
                    ((unsigned)((wn*32 + (lane & 7) + ((lane >> 4) << 3))*TILE_ST) +
                     ((lane >> 3) & 1)*4u)*4u;

    int nk = K >> 5;
    load_tile(smem, smem + TILE_A_W, A, BT, lda, ldb, m0, n0, 0, tid);

    for (int it = 0; it < nk; it++) {
        asm volatile("cp.async.wait_group 0;");
        __syncthreads();
        int cur = it & 1;
        if (it + 1 < nk)
            load_tile(smem + (cur^1)*BUF_W, smem + (cur^1)*BUF_W + TILE_A_W,
                      A, BT, lda, ldb, m0, n0, (it+1)*32, tid);
        unsigned ubuf = sbase + (unsigned)cur*BUF_W*4u;
#pragma unroll
        for (int kk = 0; kk < 4; kk++) {
            unsigned kbb = (unsigned)(kk*8)*4u;
            unsigned af[2][4], bf[4][2];
#pragma unroll
            for (int mt = 0; mt < 2; mt++) {
                unsigned addr = ubuf + aoff + (unsigned)(mt*16*TILE_ST)*4u + kbb;
                asm volatile("ldmatrix.sync.aligned.m8n8.x4.shared.b16 {%0,%1,%2,%3}, [%4];"
                    : "=r"(af[mt][0]), "=r"(af[mt][1]), "=r"(af[mt][2]), "=r"(af[mt][3])
                    : "r"(addr));
            }
#pragma unroll
            for (int p = 0; p < 2; p++) {
                unsigned addr = ubuf + boff + (unsigned)(p*16*TILE_ST)*4u + kbb;
                asm volatile("ldmatrix.sync.aligned.m8n8.x4.shared.b16 {%0,%1,%2,%3}, [%4];"
                    : "=r"(bf[2*p][0]), "=r"(bf[2*p][1]), "=r"(bf[2*p+1][0]), "=r"(bf[2*p+1][1])
                    : "r"(addr));
            }
#pragma unroll
            for (int mt = 0; mt < 2; mt++)
#pragma unroll
                for (int nt = 0; nt < 4; nt++)
                    asm volatile(
                        "mma.sync.aligned.m16n8k8.row.col.f32.tf32.tf32.f32 "
                        "{%0,%1,%2,%3}, {%4,%5,%6,%7}, {%8,%9}, {%0,%1,%2,%3};"
                        : "+f"(acc[mt][nt][0]), "+f"(acc[mt][nt][1]),
                          "+f"(acc[mt][nt][2]), "+f"(acc[mt][nt][3])
                        : "r"(af[mt][0]), "r"(af[mt][1]), "r"(af[mt][2]), "r"(af[mt][3]),
                          "r"(bf[nt][0]), "r"(bf[nt][1]));
        }
    }
    float cs[4][2] = {}, cs2[4][2] = {};
#pragma unroll
    for (int mt = 0; mt < 2; mt++) {
#pragma unroll
        for (int nt = 0; nt < 4; nt++) {
            int r = m0 + wm*32 + mt*16 + (lane >> 2);
            int c = n0 + wn*32 + nt*8 + (lane & 3)*2;
#pragma unroll
            for (int half = 0; half < 2; half++) {
                int rr = r + half*8;
                float v0 = acc[mt][nt][half*2+0];
                float v1 = acc[mt][nt][half*2+1];
                if (bias)  { v0 += bias[c];  v1 += bias[c+1]; }
                if (relu)  { v0 = fmaxf(v0, 0.0f); v1 = fmaxf(v1, 0.0f); }
                if (resid) {
                    float2 rv = *(const float2*)&resid[(size_t)rr*ldr + c];
                    v0 += rv.x; v1 += rv.y;
                }
                *(float2*)&C[(size_t)rr*ldc + c] = make_float2(v0, v1);
                if (stats) {
                    cs[nt][0]  += v0;    cs[nt][1]  += v1;
                    cs2[nt][0] += v0*v0; cs2[nt][1] += v1*v1;
                }
            }
        }
    }
    if (stats) {
        float* red = smem;              // 64 sums + 64 sumsq
        __syncthreads();
        if (tid < 128) red[tid] = 0.0f;
        __syncthreads();
#pragma unroll
        for (int nt = 0; nt < 4; nt++) {
#pragma unroll
            for (int j = 0; j < 2; j++) {
                float s = cs[nt][j], s2 = cs2[nt][j];
#pragma unroll
                for (int o = 16; o >= 4; o >>= 1) {
                    s  += __shfl_xor_sync(0xffffffffu, s,  o);
                    s2 += __shfl_xor_sync(0xffffffffu, s2, o);
                }
                if ((lane >> 2) == 0) {
                    int cc = wn*32 + nt*8 + (lane & 3)*2 + j;   // 0..63
                    atomicAdd(&red[cc], s);
                    atomicAdd(&red[64 + cc], s2);
                }
            }
        }
        __syncthreads();
        if (tid < 64) {
            atomicAdd(&stats[n0 + tid],      red[tid]);
            atomicAdd(&stats[EE + n0 + tid], red[64 + tid]);
        }
    }
}

__device__ __forceinline__ bool adj_fn(int g, int q, int k, int len, const int* fl) {
    if (q == k) return q < len;
    if (g == 0) {
        if (k == q+1) return fl[q] == 100 && q < len-1;
        if (q == k+1) return fl[k] == 100 && k < len-1;
        return false;
    } else if (g == 1) {
        if (k == q+1) return fl[q] == 100 && q < len-1;
        if (q == k+1) return fl[k] == 100 && k < len-1;
        if (k == q+2) return fl[q] == 100 && fl[q+1] == 100 && q < len-2;
        if (q == k+2) return fl[k] == 100 && fl[k+1] == 100 && k < len-2;
        return false;
    } else {
        if (q == 0 && k == len-1 && len > 1) return true;
        if (k == 0 && q == len-1 && len > 1) return true;
        if (k == q+1) return fl[q] == 101 && q < len-1;
        if (q == k+1) return fl[k] == 101 && k < len-1;
        return false;
    }
}

__global__ void __launch_bounds__(256) attn_kernel(
    const float* __restrict__ qkv, float* __restrict__ xh)
{
    __shared__ float sPart[8][32];
    __shared__ float sVmean[32];
    __shared__ int   sFlag[SS];
    __shared__ int   sLenS;
    int b = blockIdx.x, h = blockIdx.y, g = blockIdx.z;
    int tid = threadIdx.x;
    if (b == 0 && h == 0 && g == 0) {
        g_sums[tid] = 0.0f; g_sums[256+tid] = 0.0f;
        g_sums[512+tid] = 0.0f; g_sums[768+tid] = 0.0f;
    }
    const float* basep = qkv + (size_t)b*SS*QKVW + g*768 + h*DKK;
    {
        int d = tid & 31, ch = tid >> 5;
        float s = 0.0f;
        for (int r = ch*32; r < ch*32 + 32; r++)
            s += basep[(size_t)r*QKVW + 512 + d];
        sPart[ch][d] = s;
    }
    sFlag[tid] = g_flag[b*SS + tid];
    if (tid == 0) sLenS = g_len[b];
    __syncthreads();
    if (tid < 32) {
        float s = 0.0f;
#pragma unroll
        for (int c2 = 0; c2 < 8; c2++) s += sPart[c2][tid];
        sVmean[tid] = rtf(s * (1.0f/256.0f));
    }
    __syncthreads();
    int qi = tid, len = sLenS;
    float* op = xh + (size_t)(b*SS + qi)*XHW + 256 + g*256 + h*DKK;
    if (qi >= len) {
#pragma unroll
        for (int j = 0; j < 8; j++)
            *(float4*)(op + j*4) = *(float4*)(&sVmean[j*4]);
        return;
    }
    float qr[32];
    const float* qp = basep + (size_t)qi*QKVW;
#pragma unroll
    for (int j = 0; j < 8; j++) {
        float4 t4 = *(const float4*)(qp + j*4);
        qr[j*4+0] = t4.x; qr[j*4+1] = t4.y; qr[j*4+2] = t4.z; qr[j*4+3] = t4.w;
    }
    int cand[8]; int nc = 0;
    int pot[7];  int np = 0;
    if (g == 2) pot[np++] = 0;
    pot[np++] = qi-2; pot[np++] = qi-1; pot[np++] = qi; pot[np++] = qi+1; pot[np++] = qi+2;
    if (g == 2) pot[np++] = len-1;
    for (int i = 0; i < np; i++) {
        int kk = pot[i];
        if (kk < 0 || kk >= SS) continue;
        if (!adj_fn(g, qi, kk, len, sFlag)) continue;
        bool dup = false;
        for (int u = 0; u < nc; u++) if (cand[u] == kk) dup = true;
        if (!dup) cand[nc++] = kk;
    }
    const float scale = 0.17677669529663687f;
    float lg[8];
    float m = -1e30f;
    for (int i = 0; i < nc; i++) {
        const float* kp = basep + (size_t)cand[i]*QKVW + 256;
        float dot = 0.0f;
#pragma unroll
        for (int j = 0; j < 8; j++) {
            float4 k4 = *(const float4*)(kp + j*4);
            dot += qr[j*4+0]*k4.x + qr[j*4+1]*k4.y + qr[j*4+2]*k4.z + qr[j*4+3]*k4.w;
        }
        lg[i] = dot * scale;
        m = fmaxf(m, lg[i]);
    }
    float ssum = 0.0f;
    float o[32];
#pragma unroll
    for (int d = 0; d < 32; d++) o[d] = 0.0f;
    for (int i = 0; i < nc; i++) {
        float p = __expf(lg[i] - m);
        ssum += p;
        const float* vp = basep + (size_t)cand[i]*QKVW + 512;
#pragma unroll
        for (int j = 0; j < 8; j++) {
            float4 v4 = *(const float4*)(vp + j*4);
            o[j*4+0] += p*v4.x; o[j*4+1] += p*v4.y; o[j*4+2] += p*v4.z; o[j*4+3] += p*v4.w;
        }
    }
    float inv = 1.0f / ssum;
#pragma unroll
    for (int j = 0; j < 8; j++) {
        float4 w4 = make_float4(rtf(o[j*4+0]*inv), rtf(o[j*4+1]*inv),
                                rtf(o[j*4+2]*inv), rtf(o[j*4+3]*inv));
        *(float4*)(op + j*4) = w4;
    }
}

__global__ void __launch_bounds__(256) bn_norm_kernel(
    const float* __restrict__ in, float* __restrict__ outp,
    const float* __restrict__ gamma, const float* __restrict__ beta,
    const float* __restrict__ sums, int out_ld)
{
    int tid = threadIdx.x;
    int f = (tid & 63)*4;
    int t = blockIdx.x*4 + (tid >> 6);
    float4 s  = *(const float4*)&sums[f];
    float4 s2 = *(const float4*)&sums[EE + f];
    const float invN = 1.0f/(float)TT;
    float m0 = s.x*invN, m1 = s.y*invN, m2 = s.z*invN, m3 = s.w*invN;
    float r0 = rsqrtf(s2.x*invN - m0*m0 + 1e-5f);
    float r1 = rsqrtf(s2.y*invN - m1*m1 + 1e-5f);
    float r2 = rsqrtf(s2.z*invN - m2*m2 + 1e-5f);
    float r3 = rsqrtf(s2.w*invN - m3*m3 + 1e-5f);
    float4 v  = *(const float4*)&in[(size_t)t*EE + f];
    float4 gm = *(const float4*)&gamma[f];
    float4 bt = *(const float4*)&beta[f];
    float4 o;
    o.x = rtf(gm.x*(v.x - m0)*r0 + bt.x);
    o.y = rtf(gm.y*(v.y - m1)*r1 + bt.y);
    o.z = rtf(gm.z*(v.z - m2)*r2 + bt.z);
    o.w = rtf(gm.w*(v.w - m3)*r3 + bt.w);
    *(float4*)&outp[(size_t)t*out_ld + f] = o;
}

__global__ void final_kernel(const float* __restrict__ mask, float* __restrict__ outp) {
    __shared__ float sM[SS];
    int b = blockIdx.x, e = threadIdx.x;
    sM[e] = mask[b*SS + e];
    __syncthreads();
    float acc = 0.0f;
    for (int s = 0; s < SS; s++) acc += g_xh[(size_t)(b*SS + s)*XHW + e]*sM[s];
    float denom = fmaxf((float)g_len[b], 1.0f);
    outp[b*EE + e] = acc/denom;
}

extern "C" void kernel_launch(void* const* d_in, const int* in_sizes, int n_in,
                              void* d_out, int out_size) {
    (void)in_sizes; (void)n_in; (void)out_size;
    const float* data = (const float*)d_in[0];
    const float* mask = (const float*)d_in[1];
    const float* Wc   = (const float*)d_in[2];
    const float* bc   = (const float*)d_in[3];
    const float* ftab = (const float*)d_in[4];
    const float* ptab = (const float*)d_in[5];
    const float* Wq   = (const float*)d_in[6];
    const float* Wk   = (const float*)d_in[7];
    const float* Wv   = (const float*)d_in[8];
    const float* Wo   = (const float*)d_in[9];
    const float* Wf   = (const float*)d_in[10];
    const float* bf   = (const float*)d_in[11];
    const float* g1   = (const float*)d_in[12];
    const float* b1   = (const float*)d_in[13];
    const float* Wff  = (const float*)d_in[14];
    const float* bff  = (const float*)d_in[15];
    const float* g2   = (const float*)d_in[16];
    const float* b2   = (const float*)d_in[17];
    float* outp = (float*)d_out;

    float *xh, *qkv, *h, *h2, *wqkvT, *wfT, *wffT, *woR, *wcomb, *wbigT, *sums;
    cudaGetSymbolAddress((void**)&xh,    g_xh);
    cudaGetSymbolAddress((void**)&qkv,   g_qkv);
    cudaGetSymbolAddress((void**)&h,     g_h);
    cudaGetSymbolAddress((void**)&h2,    g_h2);
    cudaGetSymbolAddress((void**)&wqkvT, g_wqkvT);
    cudaGetSymbolAddress((void**)&wfT,   g_wfT);
    cudaGetSymbolAddress((void**)&wffT,  g_wffT);
    cudaGetSymbolAddress((void**)&woR,   g_woR);
    cudaGetSymbolAddress((void**)&wcomb, g_wcomb);
    cudaGetSymbolAddress((void**)&wbigT, g_wbigT);
    cudaGetSymbolAddress((void**)&sums,  g_sums);

    cudaFuncSetAttribute(mma_gemm, cudaFuncAttributeMaxDynamicSharedMemorySize, GEMM_SMEM);

    prep_w<<<(3*N_PACK + LL*EE*EE)/256, 256>>>(Wq, Wk, Wv, Wo, Wf, Wff);
    mma_gemm<<<dim3(4, 2, 12), 256, GEMM_SMEM>>>(
        woR, wfT, wcomb, EE, EE, EE, EE, nullptr, nullptr, 0, 0,
        (size_t)EE*EE, (size_t)EE*EE, (size_t)EE*EE, nullptr);
    assemble_wbigT<<<(LL*EE*XHW)/256, 256>>>(Wf);

    flags_kernel<<<BB, SS>>>(data, mask);
    embed_kernel<<<TT, EE>>>(data, Wc, bc, ftab, ptab);

    for (int l = 0; l < LL; l++) {
        mma_gemm<<<dim3(QKVW/64, TT/128, 1), 256, GEMM_SMEM>>>(
            xh, wqkvT + (size_t)l*QKVW*EE, qkv,
            EE, XHW, EE, QKVW, nullptr, nullptr, 0, 0, 0, 0, 0, nullptr);
        attn_kernel<<<dim3(BB, HH, 3), 256>>>(qkv, xh);
        mma_gemm<<<dim3(EE/64, TT/128, 1), 256, GEMM_SMEM>>>(
            xh, wbigT + (size_t)l*EE*XHW, h,
            XHW, XHW, XHW, EE, bf + l*EE, nullptr, 0, 0, 0, 0, 0, sums);
        bn_norm_kernel<<<TT/4, 256>>>(h, h, g1 + l*EE, b1 + l*EE, sums, EE);
        mma_gemm<<<dim3(EE/64, TT/128, 1), 256, GEMM_SMEM>>>(
            h, wffT + (size_t)l*EE*EE, h2,
            EE, EE, EE, EE, bff + l*EE, h, EE, 1, 0, 0, 0, sums + 2*EE);
        bn_norm_kernel<<<TT/4, 256>>>(h2, xh, g2 + l*EE, b2 + l*EE, sums + 2*EE, XHW);
    }
    final_kernel<<<BB, EE>>>(mask, outp);
}

// round 16
// speedup vs baseline: 1.0447x; 1.0447x over previous
#include <cuda_runtime.h>

#define BB 32
#define SS 256
#define EE 256
#define HH 8
#define DKK 32
#define LL 4
#define TT (BB*SS)
#define E3 (3*EE)
#define QKVW 2304
#define XHW 1024

__device__ float g_xh[TT*XHW];
__device__ float g_qkv[TT*QKVW];
__device__ float g_h[TT*EE];
__device__ float g_h2[TT*EE];
__device__ float g_wqkvT[LL*QKVW*EE];
__device__ float g_wfT[12*EE*EE];
__device__ float g_wffT[LL*EE*EE];
__device__ float g_woR[12*EE*EE];
__device__ float g_wcomb[12*EE*EE];
__device__ float g_wbigT[LL*EE*XHW];
__device__ int   g_flag[TT];
__device__ int   g_len[BB];
__device__ float g_sums[4*EE];

__device__ __forceinline__ unsigned f2tf(float x) {
    unsigned r; asm("cvt.rna.tf32.f32 %0, %1;" : "=r"(r) : "f"(x)); return r;
}
__device__ __forceinline__ float rtf(float x) { return __uint_as_float(f2tf(x)); }

#define N_PACK (12*HH*EE*DKK)
__global__ void prep_w(const float* __restrict__ Wq, const float* __restrict__ Wk,
                       const float* __restrict__ Wv, const float* __restrict__ Wo,
                       const float* __restrict__ Wf, const float* __restrict__ Wff) {
    int id = blockIdx.x*blockDim.x + threadIdx.x;
    if (id < N_PACK) {
        int d  = id % DKK;
        int e  = (id / DKK) % EE;
        int h  = (id / (DKK*EE)) % HH;
        int lg = id / (DKK*EE*HH);
        int l = lg / 3, g = lg % 3;
        int col = g*768 + h*DKK + d;
        size_t base = (size_t)l*QKVW*EE;
        g_wqkvT[base + (size_t)(col +   0)*EE + e] = rtf(Wq[id]);
        g_wqkvT[base + (size_t)(col + 256)*EE + e] = rtf(Wk[id]);
        g_wqkvT[base + (size_t)(col + 512)*EE + e] = rtf(Wv[id]);
    } else if (id < 2*N_PACK) {
        int i = id - N_PACK;
        g_woR[i] = rtf(Wo[i]);
    } else if (id < 3*N_PACK) {
        int i = id - 2*N_PACK;
        int j = i % EE, n = (i/EE) % EE, z = i/(EE*EE);
        int l = z/3, g = z%3;
        g_wfT[i] = rtf(Wf[(size_t)l*E3*EE + (size_t)(g*256+j)*EE + n]);
    } else {
        int i = id - 3*N_PACK;
        int k = i % EE, n = (i/EE) % EE, l = i/(EE*EE);
        g_wffT[i] = rtf(Wff[(size_t)l*EE*EE + (size_t)k*EE + n]);
    }
}
__global__ void assemble_wbigT(const float* __restrict__ Wf) {
    int id = blockIdx.x*blockDim.x + threadIdx.x;
    int r = id % XHW, n = (id/XHW) % EE, l = id/(XHW*EE);
    float v;
    if (r < 256) {
        const float* wf = Wf + (size_t)l*E3*EE;
        v = wf[(size_t)r*EE+n] + wf[(size_t)(256+r)*EE+n] + wf[(size_t)(512+r)*EE+n];
    } else {
        int g = (r-256) >> 8, d = (r-256) & 255;
        v = g_wcomb[(size_t)(l*3+g)*EE*EE + (size_t)d*EE + n];
    }
    g_wbigT[id] = rtf(v);
}

__global__ void flags_kernel(const float* __restrict__ data, const float* __restrict__ mask) {
    int b = blockIdx.x, s = threadIdx.x;
    int idx = b*SS + s;
    float mk = mask[idx];
    float p1 = data[idx*5+2], p2 = data[idx*5+3], p3 = data[idx*5+4];
    int f = 0;
    if (p1 == 1.0f) f = 100;
    if (p2 == 1.0f || p3 == 1.0f) f = 101;
    if (mk == 0.0f) f = 102;
    g_flag[idx] = f;
    __shared__ float red[SS];
    red[s] = mk;
    __syncthreads();
    for (int st = 128; st > 0; st >>= 1) {
        if (s < st) red[s] += red[s+st];
        __syncthreads();
    }
    if (s == 0) g_len[b] = (int)(red[0] + 0.5f);
}

__global__ void embed_kernel(const float* __restrict__ data, const float* __restrict__ Wc,
                             const float* __restrict__ bc, const float* __restrict__ ftab,
                             const float* __restrict__ ptab) {
    int t = blockIdx.x, e = threadIdx.x;
    float c0 = data[t*5+0], c1 = data[t*5+1];
    int fl = g_flag[t];
    int s = t & (SS-1);
    g_xh[(size_t)t*XHW + e] = rtf(c0*Wc[e] + c1*Wc[EE+e] + bc[e] + ftab[fl*EE+e] + ptab[s*EE+e]);
}

__device__ __forceinline__ void cpasync16(float* dst, const float* src) {
    unsigned s = (unsigned)__cvta_generic_to_shared(dst);
    asm volatile("cp.async.cg.shared.global [%0], [%1], 16;" :: "r"(s), "l"(src));
}
#define TILE_ST 36
#define TILE_W (128*TILE_ST)
#define BUF_W (2*TILE_W)
#define GEMM_SMEM (2*BUF_W*4)           // 73728 B; 2 CTAs/SM

// ============ variant 1: tile 128(M) x 128(N), warp-tile 64x32 (round-14) ============
__device__ __forceinline__ void load_tile128(float* bufA, float* bufB,
        const float* A, const float* BT, int lda, int ldb,
        int m0, int n0, int k0, int tid)
{
    int row = tid >> 1, c = (tid & 1)*16;
    {
        const float* src = A + (size_t)(m0 + row)*lda + k0 + c;
        float* dst = bufA + row*TILE_ST + c;
        cpasync16(dst, src);       cpasync16(dst + 4,  src + 4);
        cpasync16(dst + 8, src+8); cpasync16(dst + 12, src + 12);
    }
    {
        const float* src = BT + (size_t)(n0 + row)*ldb + k0 + c;
        float* dst = bufB + row*TILE_ST + c;
        cpasync16(dst, src);       cpasync16(dst + 4,  src + 4);
        cpasync16(dst + 8, src+8); cpasync16(dst + 12, src + 12);
    }
    asm volatile("cp.async.commit_group;");
}

__global__ void __launch_bounds__(256, 2) mma_gemm(
    const float* __restrict__ A, const float* __restrict__ BT, float* __restrict__ C,
    int K, int lda, int ldb, int ldc,
    const float* __restrict__ bias, const float* __restrict__ resid, int ldr, int relu,
    size_t batchA, size_t batchB, size_t batchC, float* stats)
{
    extern __shared__ float smem[];
    int z = blockIdx.z;
    A  += (size_t)z*batchA; BT += (size_t)z*batchB; C += (size_t)z*batchC;
    int tid = threadIdx.x, lane = tid & 31, warp = tid >> 5;
    int wm = warp & 1, wn = warp >> 1;
    int m0 = blockIdx.y*128, n0 = blockIdx.x*128;
    float acc[4][4][4];
#pragma unroll
    for (int a2 = 0; a2 < 4; a2++)
#pragma unroll
        for (int b2 = 0; b2 < 4; b2++)
#pragma unroll
            for (int c2 = 0; c2 < 4; c2++) acc[a2][b2][c2] = 0.0f;

    unsigned sbase = (unsigned)__cvta_generic_to_shared(smem);
    unsigned aoff = ((unsigned)((wm*64 + (lane & 15))*TILE_ST) + (lane >= 16 ? 4u : 0u))*4u;
    unsigned boff = (unsigned)TILE_W*4u +
                    ((unsigned)((wn*32 + (lane & 7) + ((lane >> 4) << 3))*TILE_ST) +
                     ((lane >> 3) & 1)*4u)*4u;

    int nk = K >> 5;
    load_tile128(smem, smem + TILE_W, A, BT, lda, ldb, m0, n0, 0, tid);

    for (int it = 0; it < nk; it++) {
        asm volatile("cp.async.wait_group 0;");
        __syncthreads();
        int cur = it & 1;
        if (it + 1 < nk)
            load_tile128(smem + (cur^1)*BUF_W, smem + (cur^1)*BUF_W + TILE_W,
                      A, BT, lda, ldb, m0, n0, (it+1)*32, tid);
        unsigned ubuf = sbase + (unsigned)cur*BUF_W*4u;
#pragma unroll
        for (int kk = 0; kk < 4; kk++) {
            unsigned kbb = (unsigned)(kk*8)*4u;
            unsigned af[4][4], bf[4][2];
#pragma unroll
            for (int mt = 0; mt < 4; mt++) {
                unsigned addr = ubuf + aoff + (unsigned)(mt*16*TILE_ST)*4u + kbb;
                asm volatile("ldmatrix.sync.aligned.m8n8.x4.shared.b16 {%0,%1,%2,%3}, [%4];"
                    : "=r"(af[mt][0]), "=r"(af[mt][1]), "=r"(af[mt][2]), "=r"(af[mt][3])
                    : "r"(addr));
            }
#pragma unroll
            for (int p = 0; p < 2; p++) {
                unsigned addr = ubuf + boff + (unsigned)(p*16*TILE_ST)*4u + kbb;
                asm volatile("ldmatrix.sync.aligned.m8n8.x4.shared.b16 {%0,%1,%2,%3}, [%4];"
                    : "=r"(bf[2*p][0]), "=r"(bf[2*p][1]), "=r"(bf[2*p+1][0]), "=r"(bf[2*p+1][1])
                    : "r"(addr));
            }
#pragma unroll
            for (int mt = 0; mt < 4; mt++)
#pragma unroll
                for (int nt = 0; nt < 4; nt++)
                    asm volatile(
                        "mma.sync.aligned.m16n8k8.row.col.f32.tf32.tf32.f32 "
                        "{%0,%1,%2,%3}, {%4,%5,%6,%7}, {%8,%9}, {%0,%1,%2,%3};"
                        : "+f"(acc[mt][nt][0]), "+f"(acc[mt][nt][1]),
                          "+f"(acc[mt][nt][2]), "+f"(acc[mt][nt][3])
                        : "r"(af[mt][0]), "r"(af[mt][1]), "r"(af[mt][2]), "r"(af[mt][3]),
                          "r"(bf[nt][0]), "r"(bf[nt][1]));
        }
    }
#pragma unroll
    for (int mt = 0; mt < 4; mt++) {
#pragma unroll
        for (int nt = 0; nt < 4; nt++) {
            int r = m0 + wm*64 + mt*16 + (lane >> 2);
            int c = n0 + wn*32 + nt*8 + (lane & 3)*2;
#pragma unroll
            for (int half = 0; half < 2; half++) {
                int rr = r + half*8;
                float v0 = acc[mt][nt][half*2+0];
                float v1 = acc[mt][nt][half*2+1];
                if (bias)  { v0 += bias[c];  v1 += bias[c+1]; }
                if (relu)  { v0 = fmaxf(v0, 0.0f); v1 = fmaxf(v1, 0.0f); }
                if (resid) {
                    float2 rv = *(const float2*)&resid[(size_t)rr*ldr + c];
                    v0 += rv.x; v1 += rv.y;
                }
                *(float2*)&C[(size_t)rr*ldc + c] = make_float2(v0, v1);
            }
        }
    }
    (void)stats;
}

// ============ variant 2: tile 64(M) x 128(N), warp-tile 32x32, 3 CTAs/SM ============
#define TILE_A64_W (64*TILE_ST)         // 2304 words
#define BUF64_W (TILE_A64_W + TILE_W)   // 6912 words
#define GEMM64_SMEM (2*BUF64_W*4)       // 55296 B

__device__ __forceinline__ void load_tile64(float* bufA, float* bufB,
        const float* A, const float* BT, int lda, int ldb,
        int m0, int n0, int k0, int tid)
{
    {   // A: 64 rows x 32 k; thread -> 8 floats
        int row = tid >> 2, c = (tid & 3)*8;
        const float* src = A + (size_t)(m0 + row)*lda + k0 + c;
        float* dst = bufA + row*TILE_ST + c;
        cpasync16(dst, src);  cpasync16(dst + 4, src + 4);
    }
    {   // B: 128 rows x 32 k; thread -> 16 floats
        int row = tid >> 1, c = (tid & 1)*16;
        const float* src = BT + (size_t)(n0 + row)*ldb + k0 + c;
        float* dst = bufB + row*TILE_ST + c;
        cpasync16(dst, src);       cpasync16(dst + 4,  src + 4);
        cpasync16(dst + 8, src+8); cpasync16(dst + 12, src + 12);
    }
    asm volatile("cp.async.commit_group;");
}

__global__ void __launch_bounds__(256, 3) mma_gemm64(
    const float* __restrict__ A, const float* __restrict__ BT, float* __restrict__ C,
    int K, int lda, int ldb, int ldc,
    const float* __restrict__ bias, const float* __restrict__ resid, int ldr, int relu,
    float* stats)
{
    extern __shared__ float smem[];
    int tid = threadIdx.x, lane = tid & 31, warp = tid >> 5;
    int wm = warp & 1, wn = warp >> 1;     // 2(M) x 4(N) warps, warp-tile 32x32
    int m0 = blockIdx.y*64, n0 = blockIdx.x*128;
    float acc[2][4][4];
#pragma unroll
    for (int a2 = 0; a2 < 2; a2++)
#pragma unroll
        for (int b2 = 0; b2 < 4; b2++)
#pragma unroll
            for (int c2 = 0; c2 < 4; c2++) acc[a2][b2][c2] = 0.0f;

    unsigned sbase = (unsigned)__cvta_generic_to_shared(smem);
    unsigned aoff = ((unsigned)((wm*32 + (lane & 15))*TILE_ST) + (lane >= 16 ? 4u : 0u))*4u;
    unsigned boff = (unsigned)TILE_A64_W*4u +
                    ((unsigned)((wn*32 + (lane & 7) + ((lane >> 4) << 3))*TILE_ST) +
                     ((lane >> 3) & 1)*4u)*4u;

    int nk = K >> 5;
    load_tile64(smem, smem + TILE_A64_W, A, BT, lda, ldb, m0, n0, 0, tid);

    for (int it = 0; it < nk; it++) {
        asm volatile("cp.async.wait_group 0;");
        __syncthreads();
        int cur = it & 1;
        if (it + 1 < nk)
            load_tile64(smem + (cur^1)*BUF64_W, smem + (cur^1)*BUF64_W + TILE_A64_W,
                        A, BT, lda, ldb, m0, n0, (it+1)*32, tid);
        unsigned ubuf = sbase + (unsigned)cur*BUF64_W*4u;
#pragma unroll
        for (int kk = 0; kk < 4; kk++) {
            unsigned kbb = (unsigned)(kk*8)*4u;
            unsigned af[2][4], bf[4][2];
#pragma unroll
            for (int mt = 0; mt < 2; mt++) {
                unsigned addr = ubuf + aoff + (unsigned)(mt*16*TILE_ST)*4u + kbb;
                asm volatile("ldmatrix.sync.aligned.m8n8.x4.shared.b16 {%0,%1,%2,%3}, [%4];"
                    : "=r"(af[mt][0]), "=r"(af[mt][1]), "=r"(af[mt][2]), "=r"(af[mt][3])
                    : "r"(addr));
            }
#pragma unroll
            for (int p = 0; p < 2; p++) {
                unsigned addr = ubuf + boff + (unsigned)(p*16*TILE_ST)*4u + kbb;
                asm volatile("ldmatrix.sync.aligned.m8n8.x4.shared.b16 {%0,%1,%2,%3}, [%4];"
                    : "=r"(bf[2*p][0]), "=r"(bf[2*p][1]), "=r"(bf[2*p+1][0]), "=r"(bf[2*p+1][1])
                    : "r"(addr));
            }
#pragma unroll
            for (int mt = 0; mt < 2; mt++)
#pragma unroll
                for (int nt = 0; nt < 4; nt++)
                    asm volatile(
                        "mma.sync.aligned.m16n8k8.row.col.f32.tf32.tf32.f32 "
                        "{%0,%1,%2,%3}, {%4,%5,%6,%7}, {%8,%9}, {%0,%1,%2,%3};"
                        : "+f"(acc[mt][nt][0]), "+f"(acc[mt][nt][1]),
                          "+f"(acc[mt][nt][2]), "+f"(acc[mt][nt][3])
                        : "r"(af[mt][0]), "r"(af[mt][1]), "r"(af[mt][2]), "r"(af[mt][3]),
                          "r"(bf[nt][0]), "r"(bf[nt][1]));
        }
    }
    float cs[4][2] = {}, cs2[4][2] = {};
#pragma unroll
    for (int mt = 0; mt < 2; mt++) {
#pragma unroll
        for (int nt = 0; nt < 4; nt++) {
            int r = m0 + wm*32 + mt*16 + (lane >> 2);
            int c = n0 + wn*32 + nt*8 + (lane & 3)*2;
#pragma unroll
            for (int half = 0; half < 2; half++) {
                int rr = r + half*8;
                float v0 = acc[mt][nt][half*2+0];
                float v1 = acc[mt][nt][half*2+1];
                if (bias)  { v0 += bias[c];  v1 += bias[c+1]; }
                if (relu)  { v0 = fmaxf(v0, 0.0f); v1 = fmaxf(v1, 0.0f); }
                if (resid) {
                    float2 rv = *(const float2*)&resid[(size_t)rr*ldr + c];
                    v0 += rv.x; v1 += rv.y;
                }
                *(float2*)&C[(size_t)rr*ldc + c] = make_float2(v0, v1);
                if (stats) {
                    cs[nt][0]  += v0;    cs[nt][1]  += v1;
                    cs2[nt][0] += v0*v0; cs2[nt][1] += v1*v1;
                }
            }
        }
    }
    if (stats) {
        float* red = smem;
        __syncthreads();
        if (tid < 256) red[tid] = 0.0f;
        __syncthreads();
#pragma unroll
        for (int nt = 0; nt < 4; nt++) {
#pragma unroll
            for (int j = 0; j < 2; j++) {
                float s = cs[nt][j], s2 = cs2[nt][j];
#pragma unroll
                for (int o = 16; o >= 4; o >>= 1) {
                    s  += __shfl_xor_sync(0xffffffffu, s,  o);
                    s2 += __shfl_xor_sync(0xffffffffu, s2, o);
                }
                if ((lane >> 2) == 0) {
                    int cc = wn*32 + nt*8 + (lane & 3)*2 + j;   // 0..127
                    atomicAdd(&red[cc], s);
                    atomicAdd(&red[128 + cc], s2);
                }
            }
        }
        __syncthreads();
        if (tid < 128) {
            atomicAdd(&stats[n0 + tid],      red[tid]);
            atomicAdd(&stats[EE + n0 + tid], red[128 + tid]);
        }
    }
}

__device__ __forceinline__ bool adj_fn(int g, int q, int k, int len, const int* fl) {
    if (q == k) return q < len;
    if (g == 0) {
        if (k == q+1) return fl[q] == 100 && q < len-1;
        if (q == k+1) return fl[k] == 100 && k < len-1;
        return false;
    } else if (g == 1) {
        if (k == q+1) return fl[q] == 100 && q < len-1;
        if (q == k+1) return fl[k] == 100 && k < len-1;
        if (k == q+2) return fl[q] == 100 && fl[q+1] == 100 && q < len-2;
        if (q == k+2) return fl[k] == 100 && fl[k+1] == 100 && k < len-2;
        return false;
    } else {
        if (q == 0 && k == len-1 && len > 1) return true;
        if (k == 0 && q == len-1 && len > 1) return true;
        if (k == q+1) return fl[q] == 101 && q < len-1;
        if (q == k+1) return fl[k] == 101 && k < len-1;
        return false;
    }
}

__global__ void __launch_bounds__(256) attn_kernel(
    const float* __restrict__ qkv, float* __restrict__ xh)
{
    __shared__ float sPart[8][32];
    __shared__ float sVmean[32];
    __shared__ int   sFlag[SS];
    __shared__ int   sLenS;
    int b = blockIdx.x, h = blockIdx.y, g = blockIdx.z;
    int tid = threadIdx.x;
    if (b == 0 && h == 0 && g == 0) {
        g_sums[tid] = 0.0f; g_sums[256+tid] = 0.0f;
        g_sums[512+tid] = 0.0f; g_sums[768+tid] = 0.0f;
    }
    const float* basep = qkv + (size_t)b*SS*QKVW + g*768 + h*DKK;
    {
        int d = tid & 31, ch = tid >> 5;
        float s = 0.0f;
        for (int r = ch*32; r < ch*32 + 32; r++)
            s += basep[(size_t)r*QKVW + 512 + d];
        sPart[ch][d] = s;
    }
    sFlag[tid] = g_flag[b*SS + tid];
    if (tid == 0) sLenS = g_len[b];
    __syncthreads();
    if (tid < 32) {
        float s = 0.0f;
#pragma unroll
        for (int c2 = 0; c2 < 8; c2++) s += sPart[c2][tid];
        sVmean[tid] = rtf(s * (1.0f/256.0f));
    }
    __syncthreads();
    int qi = tid, len = sLenS;
    float* op = xh + (size_t)(b*SS + qi)*XHW + 256 + g*256 + h*DKK;
    if (qi >= len) {
#pragma unroll
        for (int j = 0; j < 8; j++)
            *(float4*)(op + j*4) = *(float4*)(&sVmean[j*4]);
        return;
    }
    float qr[32];
    const float* qp = basep + (size_t)qi*QKVW;
#pragma unroll
    for (int j = 0; j < 8; j++) {
        float4 t4 = *(const float4*)(qp + j*4);
        qr[j*4+0] = t4.x; qr[j*4+1] = t4.y; qr[j*4+2] = t4.z; qr[j*4+3] = t4.w;
    }
    int cand[8]; int nc = 0;
    int pot[7];  int np = 0;
    if (g == 2) pot[np++] = 0;
    pot[np++] = qi-2; pot[np++] = qi-1; pot[np++] = qi; pot[np++] = qi+1; pot[np++] = qi+2;
    if (g == 2) pot[np++] = len-1;
    for (int i = 0; i < np; i++) {
        int kk = pot[i];
        if (kk < 0 || kk >= SS) continue;
        if (!adj_fn(g, qi, kk, len, sFlag)) continue;
        bool dup = false;
        for (int u = 0; u < nc; u++) if (cand[u] == kk) dup = true;
        if (!dup) cand[nc++] = kk;
    }
    const float scale = 0.17677669529663687f;
    float lg[8];
    float m = -1e30f;
    for (int i = 0; i < nc; i++) {
        const float* kp = basep + (size_t)cand[i]*QKVW + 256;
        float dot = 0.0f;
#pragma unroll
        for (int j = 0; j < 8; j++) {
            float4 k4 = *(const float4*)(kp + j*4);
            dot += qr[j*4+0]*k4.x + qr[j*4+1]*k4.y + qr[j*4+2]*k4.z + qr[j*4+3]*k4.w;
        }
        lg[i] = dot * scale;
        m = fmaxf(m, lg[i]);
    }
    float ssum = 0.0f;
    float o[32];
#pragma unroll
    for (int d = 0; d < 32; d++) o[d] = 0.0f;
    for (int i = 0; i < nc; i++) {
        float p = __expf(lg[i] - m);
        ssum += p;
        const float* vp = basep + (size_t)cand[i]*QKVW + 512;
#pragma unroll
        for (int j = 0; j < 8; j++) {
            float4 v4 = *(const float4*)(vp + j*4);
            o[j*4+0] += p*v4.x; o[j*4+1] += p*v4.y; o[j*4+2] += p*v4.z; o[j*4+3] += p*v4.w;
        }
    }
    float inv = 1.0f / ssum;
#pragma unroll
    for (int j = 0; j < 8; j++) {
        float4 w4 = make_float4(rtf(o[j*4+0]*inv), rtf(o[j*4+1]*inv),
                                rtf(o[j*4+2]*inv), rtf(o[j*4+3]*inv));
        *(float4*)(op + j*4) = w4;
    }
}

__global__ void __launch_bounds__(256) bn_norm_kernel(
    const float* __restrict__ in, float* __restrict__ outp,
    const float* __restrict__ gamma, const float* __restrict__ beta,
    const float* __restrict__ sums, int out_ld)
{
    int tid = threadIdx.x;
    int f = (tid & 63)*4;
    int t = blockIdx.x*4 + (tid >> 6);
    float4 s  = *(const float4*)&sums[f];
    float4 s2 = *(const float4*)&sums[EE + f];
    const float invN = 1.0f/(float)TT;
    float m0 = s.x*invN, m1 = s.y*invN, m2 = s.z*invN, m3 = s.w*invN;
    float r0 = rsqrtf(s2.x*invN - m0*m0 + 1e-5f);
    float r1 = rsqrtf(s2.y*invN - m1*m1 + 1e-5f);
    float r2 = rsqrtf(s2.z*invN - m2*m2 + 1e-5f);
    float r3 = rsqrtf(s2.w*invN - m3*m3 + 1e-5f);
    float4 v  = *(const float4*)&in[(size_t)t*EE + f];
    float4 gm = *(const float4*)&gamma[f];
    float4 bt = *(const float4*)&beta[f];
    float4 o;
    o.x = rtf(gm.x*(v.x - m0)*r0 + bt.x);
    o.y = rtf(gm.y*(v.y - m1)*r1 + bt.y);
    o.z = rtf(gm.z*(v.z - m2)*r2 + bt.z);
    o.w = rtf(gm.w*(v.w - m3)*r3 + bt.w);
    *(float4*)&outp[(size_t)t*out_ld + f] = o;
}

__global__ void final_kernel(const float* __restrict__ mask, float* __restrict__ outp) {
    __shared__ float sM[SS];
    int b = blockIdx.x, e = threadIdx.x;
    sM[e] = mask[b*SS + e];
    __syncthreads();
    float acc = 0.0f;
    for (int s = 0; s < SS; s++) acc += g_xh[(size_t)(b*SS + s)*XHW + e]*sM[s];
    float denom = fmaxf((float)g_len[b], 1.0f);
    outp[b*EE + e] = acc/denom;
}

extern "C" void kernel_launch(void* const* d_in, const int* in_sizes, int n_in,
                              void* d_out, int out_size) {
    (void)in_sizes; (void)n_in; (void)out_size;
    const float* data = (const float*)d_in[0];
    const float* mask = (const float*)d_in[1];
    const float* Wc   = (const float*)d_in[2];
    const float* bc   = (const float*)d_in[3];
    const float* ftab = (const float*)d_in[4];
    const float* ptab = (const float*)d_in[5];
    const float* Wq   = (const float*)d_in[6];
    const float* Wk   = (const float*)d_in[7];
    const float* Wv   = (const float*)d_in[8];
    const float* Wo   = (const float*)d_in[9];
    const float* Wf   = (const float*)d_in[10];
    const float* bf   = (const float*)d_in[11];
    const float* g1   = (const float*)d_in[12];
    const float* b1   = (const float*)d_in[13];
    const float* Wff  = (const float*)d_in[14];
    const float* bff  = (const float*)d_in[15];
    const float* g2   = (const float*)d_in[16];
    const float* b2   = (const float*)d_in[17];
    float* outp = (float*)d_out;

    float *xh, *qkv, *h, *h2, *wqkvT, *wfT, *wffT, *woR, *wcomb, *wbigT, *sums;
    cudaGetSymbolAddress((void**)&xh,    g_xh);
    cudaGetSymbolAddress((void**)&qkv,   g_qkv);
    cudaGetSymbolAddress((void**)&h,     g_h);
    cudaGetSymbolAddress((void**)&h2,    g_h2);
    cudaGetSymbolAddress((void**)&wqkvT, g_wqkvT);
    cudaGetSymbolAddress((void**)&wfT,   g_wfT);
    cudaGetSymbolAddress((void**)&wffT,  g_wffT);
    cudaGetSymbolAddress((void**)&woR,   g_woR);
    cudaGetSymbolAddress((void**)&wcomb, g_wcomb);
    cudaGetSymbolAddress((void**)&wbigT, g_wbigT);
    cudaGetSymbolAddress((void**)&sums,  g_sums);

    cudaFuncSetAttribute(mma_gemm,   cudaFuncAttributeMaxDynamicSharedMemorySize, GEMM_SMEM);
    cudaFuncSetAttribute(mma_gemm64, cudaFuncAttributeMaxDynamicSharedMemorySize, GEMM64_SMEM);

    prep_w<<<(3*N_PACK + LL*EE*EE)/256, 256>>>(Wq, Wk, Wv, Wo, Wf, Wff);
    mma_gemm<<<dim3(2, 2, 12), 256, GEMM_SMEM>>>(
        woR, wfT, wcomb, EE, EE, EE, EE, nullptr, nullptr, 0, 0,
        (size_t)EE*EE, (size_t)EE*EE, (size_t)EE*EE, nullptr);
    assemble_wbigT<<<(LL*EE*XHW)/256, 256>>>(Wf);

    flags_kernel<<<BB, SS>>>(data, mask);
    embed_kernel<<<TT, EE>>>(data, Wc, bc, ftab, ptab);

    for (int l = 0; l < LL; l++) {
        mma_gemm<<<dim3(QKVW/128, TT/128, 1), 256, GEMM_SMEM>>>(
            xh, wqkvT + (size_t)l*QKVW*EE, qkv,
            EE, XHW, EE, QKVW, nullptr, nullptr, 0, 0, 0, 0, 0, nullptr);
        attn_kernel<<<dim3(BB, HH, 3), 256>>>(qkv, xh);
        mma_gemm64<<<dim3(EE/128, TT/64, 1), 256, GEMM64_SMEM>>>(
            xh, wbigT + (size_t)l*EE*XHW, h,
            XHW, XHW, XHW, EE, bf + l*EE, nullptr, 0, 0, sums);
        bn_norm_kernel<<<TT/4, 256>>>(h, h, g1 + l*EE, b1 + l*EE, sums, EE);
        mma_gemm64<<<dim3(EE/128, TT/64, 1), 256, GEMM64_SMEM>>>(
            h, wffT + (size_t)l*EE*EE, h2,
            EE, EE, EE, EE, bff + l*EE, h, EE, 1, sums + 2*EE);
        bn_norm_kernel<<<TT/4, 256>>>(h2, xh, g2 + l*EE, b2 + l*EE, sums + 2*EE, XHW);
    }
    final_kernel<<<BB, EE>>>(mask, outp);
}

// round 17
// speedup vs baseline: 1.0547x; 1.0096x over previous
#include <cuda_runtime.h>

#define BB 32
#define SS 256
#define EE 256
#define HH 8
#define DKK 32
#define LL 4
#define TT (BB*SS)
#define E3 (3*EE)
#define QKVW 2304
#define XHW 1024

__device__ float g_xh[TT*XHW];
__device__ float g_qkv[TT*QKVW];
__device__ float g_h[TT*EE];
__device__ float g_h2[TT*EE];
__device__ float g_wqkvT[LL*QKVW*EE];
__device__ float g_wfT[12*EE*EE];
__device__ float g_wffT[LL*EE*EE];
__device__ float g_woR[12*EE*EE];
__device__ float g_wcomb[12*EE*EE];
__device__ float g_wbigT[LL*EE*XHW];
__device__ int   g_flag[TT];
__device__ int   g_len[BB];
__device__ float g_sums[4*EE];
__device__ float g_bnA[EE];
__device__ float g_bnC[EE];
__device__ float g_bias2[EE];

__device__ __forceinline__ unsigned f2tf(float x) {
    unsigned r; asm("cvt.rna.tf32.f32 %0, %1;" : "=r"(r) : "f"(x)); return r;
}
__device__ __forceinline__ float rtf(float x) { return __uint_as_float(f2tf(x)); }

#define N_PACK (12*HH*EE*DKK)
__global__ void prep_w(const float* __restrict__ Wq, const float* __restrict__ Wk,
                       const float* __restrict__ Wv, const float* __restrict__ Wo,
                       const float* __restrict__ Wf, const float* __restrict__ Wff) {
    int id = blockIdx.x*blockDim.x + threadIdx.x;
    if (id < N_PACK) {
        int d  = id % DKK;
        int e  = (id / DKK) % EE;
        int h  = (id / (DKK*EE)) % HH;
        int lg = id / (DKK*EE*HH);
        int l = lg / 3, g = lg % 3;
        int col = g*768 + h*DKK + d;
        size_t base = (size_t)l*QKVW*EE;
        g_wqkvT[base + (size_t)(col +   0)*EE + e] = rtf(Wq[id]);
        g_wqkvT[base + (size_t)(col + 256)*EE + e] = rtf(Wk[id]);
        g_wqkvT[base + (size_t)(col + 512)*EE + e] = rtf(Wv[id]);
    } else if (id < 2*N_PACK) {
        int i = id - N_PACK;
        g_woR[i] = rtf(Wo[i]);
    } else if (id < 3*N_PACK) {
        int i = id - 2*N_PACK;
        int j = i % EE, n = (i/EE) % EE, z = i/(EE*EE);
        int l = z/3, g = z%3;
        g_wfT[i] = rtf(Wf[(size_t)l*E3*EE + (size_t)(g*256+j)*EE + n]);
    } else {
        int i = id - 3*N_PACK;
        int k = i % EE, n = (i/EE) % EE, l = i/(EE*EE);
        g_wffT[i] = rtf(Wff[(size_t)l*EE*EE + (size_t)k*EE + n]);
    }
}
__global__ void assemble_wbigT(const float* __restrict__ Wf) {
    int id = blockIdx.x*blockDim.x + threadIdx.x;
    int r = id % XHW, n = (id/XHW) % EE, l = id/(XHW*EE);
    float v;
    if (r < 256) {
        const float* wf = Wf + (size_t)l*E3*EE;
        v = wf[(size_t)r*EE+n] + wf[(size_t)(256+r)*EE+n] + wf[(size_t)(512+r)*EE+n];
    } else {
        int g = (r-256) >> 8, d = (r-256) & 255;
        v = g_wcomb[(size_t)(l*3+g)*EE*EE + (size_t)d*EE + n];
    }
    g_wbigT[id] = rtf(v);
}

__global__ void flags_kernel(const float* __restrict__ data, const float* __restrict__ mask) {
    int b = blockIdx.x, s = threadIdx.x;
    int idx = b*SS + s;
    float mk = mask[idx];
    float p1 = data[idx*5+2], p2 = data[idx*5+3], p3 = data[idx*5+4];
    int f = 0;
    if (p1 == 1.0f) f = 100;
    if (p2 == 1.0f || p3 == 1.0f) f = 101;
    if (mk == 0.0f) f = 102;
    g_flag[idx] = f;
    __shared__ float red[SS];
    red[s] = mk;
    __syncthreads();
    for (int st = 128; st > 0; st >>= 1) {
        if (s < st) red[s] += red[s+st];
        __syncthreads();
    }
    if (s == 0) g_len[b] = (int)(red[0] + 0.5f);
}

__global__ void embed_kernel(const float* __restrict__ data, const float* __restrict__ Wc,
                             const float* __restrict__ bc, const float* __restrict__ ftab,
                             const float* __restrict__ ptab) {
    int t = blockIdx.x, e = threadIdx.x;
    float c0 = data[t*5+0], c1 = data[t*5+1];
    int fl = g_flag[t];
    int s = t & (SS-1);
    g_xh[(size_t)t*XHW + e] = rtf(c0*Wc[e] + c1*Wc[EE+e] + bc[e] + ftab[fl*EE+e] + ptab[s*EE+e]);
}

__device__ __forceinline__ void cpasync16(float* dst, const float* src) {
    unsigned s = (unsigned)__cvta_generic_to_shared(dst);
    asm volatile("cp.async.cg.shared.global [%0], [%1], 16;" :: "r"(s), "l"(src));
}
#define TILE_ST 36
#define TILE_W (128*TILE_ST)
#define BUF_W (2*TILE_W)
#define GEMM_SMEM (2*BUF_W*4)               // 73728 B
#define GEMM_AFF_SMEM ((2*BUF_W + 512)*4)   // + a[256], c[256]

__device__ __forceinline__ void load_tile128(float* bufA, float* bufB,
        const float* A, const float* BT, int lda, int ldb,
        int m0, int n0, int k0, int tid)
{
    int row = tid >> 1, c = (tid & 1)*16;
    {
        const float* src = A + (size_t)(m0 + row)*lda + k0 + c;
        float* dst = bufA + row*TILE_ST + c;
        cpasync16(dst, src);       cpasync16(dst + 4,  src + 4);
        cpasync16(dst + 8, src+8); cpasync16(dst + 12, src + 12);
    }
    {
        const float* src = BT + (size_t)(n0 + row)*ldb + k0 + c;
        float* dst = bufB + row*TILE_ST + c;
        cpasync16(dst, src);       cpasync16(dst + 4,  src + 4);
        cpasync16(dst + 8, src+8); cpasync16(dst + 12, src + 12);
    }
    asm volatile("cp.async.commit_group;");
}

// ======== round-14 GEMM: 128x128, warp-tile 64x32, 2 CTAs/SM, optional stats ========
__global__ void __launch_bounds__(256, 2) mma_gemm(
    const float* __restrict__ A, const float* __restrict__ BT, float* __restrict__ C,
    int K, int lda, int ldb, int ldc,
    const float* __restrict__ bias, const float* __restrict__ resid, int ldr, int relu,
    size_t batchA, size_t batchB, size_t batchC, float* stats)
{
    extern __shared__ float smem[];
    int z = blockIdx.z;
    A  += (size_t)z*batchA; BT += (size_t)z*batchB; C += (size_t)z*batchC;
    int tid = threadIdx.x, lane = tid & 31, warp = tid >> 5;
    int wm = warp & 1, wn = warp >> 1;
    int m0 = blockIdx.y*128, n0 = blockIdx.x*128;
    float acc[4][4][4];
#pragma unroll
    for (int a2 = 0; a2 < 4; a2++)
#pragma unroll
        for (int b2 = 0; b2 < 4; b2++)
#pragma unroll
            for (int c2 = 0; c2 < 4; c2++) acc[a2][b2][c2] = 0.0f;

    unsigned sbase = (unsigned)__cvta_generic_to_shared(smem);
    unsigned aoff = ((unsigned)((wm*64 + (lane & 15))*TILE_ST) + (lane >= 16 ? 4u : 0u))*4u;
    unsigned boff = (unsigned)TILE_W*4u +
                    ((unsigned)((wn*32 + (lane & 7) + ((lane >> 4) << 3))*TILE_ST) +
                     ((lane >> 3) & 1)*4u)*4u;

    int nk = K >> 5;
    load_tile128(smem, smem + TILE_W, A, BT, lda, ldb, m0, n0, 0, tid);

    for (int it = 0; it < nk; it++) {
        asm volatile("cp.async.wait_group 0;");
        __syncthreads();
        int cur = it & 1;
        if (it + 1 < nk)
            load_tile128(smem + (cur^1)*BUF_W, smem + (cur^1)*BUF_W + TILE_W,
                      A, BT, lda, ldb, m0, n0, (it+1)*32, tid);
        unsigned ubuf = sbase + (unsigned)cur*BUF_W*4u;
#pragma unroll
        for (int kk = 0; kk < 4; kk++) {
            unsigned kbb = (unsigned)(kk*8)*4u;
            unsigned af[4][4], bf[4][2];
#pragma unroll
            for (int mt = 0; mt < 4; mt++) {
                unsigned addr = ubuf + aoff + (unsigned)(mt*16*TILE_ST)*4u + kbb;
                asm volatile("ldmatrix.sync.aligned.m8n8.x4.shared.b16 {%0,%1,%2,%3}, [%4];"
                    : "=r"(af[mt][0]), "=r"(af[mt][1]), "=r"(af[mt][2]), "=r"(af[mt][3])
                    : "r"(addr));
            }
#pragma unroll
            for (int p = 0; p < 2; p++) {
                unsigned addr = ubuf + boff + (unsigned)(p*16*TILE_ST)*4u + kbb;
                asm volatile("ldmatrix.sync.aligned.m8n8.x4.shared.b16 {%0,%1,%2,%3}, [%4];"
                    : "=r"(bf[2*p][0]), "=r"(bf[2*p][1]), "=r"(bf[2*p+1][0]), "=r"(bf[2*p+1][1])
                    : "r"(addr));
            }
#pragma unroll
            for (int mt = 0; mt < 4; mt++)
#pragma unroll
                for (int nt = 0; nt < 4; nt++)
                    asm volatile(
                        "mma.sync.aligned.m16n8k8.row.col.f32.tf32.tf32.f32 "
                        "{%0,%1,%2,%3}, {%4,%5,%6,%7}, {%8,%9}, {%0,%1,%2,%3};"
                        : "+f"(acc[mt][nt][0]), "+f"(acc[mt][nt][1]),
                          "+f"(acc[mt][nt][2]), "+f"(acc[mt][nt][3])
                        : "r"(af[mt][0]), "r"(af[mt][1]), "r"(af[mt][2]), "r"(af[mt][3]),
                          "r"(bf[nt][0]), "r"(bf[nt][1]));
        }
    }
    float cs[4][2] = {}, cs2[4][2] = {};
#pragma unroll
    for (int mt = 0; mt < 4; mt++) {
#pragma unroll
        for (int nt = 0; nt < 4; nt++) {
            int r = m0 + wm*64 + mt*16 + (lane >> 2);
            int c = n0 + wn*32 + nt*8 + (lane & 3)*2;
#pragma unroll
            for (int half = 0; half < 2; half++) {
                int rr = r + half*8;
                float v0 = acc[mt][nt][half*2+0];
                float v1 = acc[mt][nt][half*2+1];
                if (bias)  { v0 += bias[c];  v1 += bias[c+1]; }
                if (relu)  { v0 = fmaxf(v0, 0.0f); v1 = fmaxf(v1, 0.0f); }
                if (resid) {
                    float2 rv = *(const float2*)&resid[(size_t)rr*ldr + c];
                    v0 += rv.x; v1 += rv.y;
                }
                *(float2*)&C[(size_t)rr*ldc + c] = make_float2(v0, v1);
                if (stats) {
                    cs[nt][0]  += v0;    cs[nt][1]  += v1;
                    cs2[nt][0] += v0*v0; cs2[nt][1] += v1*v1;
                }
            }
        }
    }
    if (stats) {
        float* red = smem;
        __syncthreads();
        if (tid < 256) red[tid] = 0.0f;
        __syncthreads();
#pragma unroll
        for (int nt = 0; nt < 4; nt++) {
#pragma unroll
            for (int j = 0; j < 2; j++) {
                float s = cs[nt][j], s2 = cs2[nt][j];
#pragma unroll
                for (int o = 16; o >= 4; o >>= 1) {
                    s  += __shfl_xor_sync(0xffffffffu, s,  o);
                    s2 += __shfl_xor_sync(0xffffffffu, s2, o);
                }
                if ((lane >> 2) == 0) {
                    int cc = wn*32 + nt*8 + (lane & 3)*2 + j;
                    atomicAdd(&red[cc], s);
                    atomicAdd(&red[128 + cc], s2);
                }
            }
        }
        __syncthreads();
        if (tid < 128) {
            atomicAdd(&stats[n0 + tid],      red[tid]);
            atomicAdd(&stats[EE + n0 + tid], red[128 + tid]);
        }
    }
}

// ======== aff variant: A scaled per-column k by a[k] (BN absorbed), resid affine ====
__global__ void __launch_bounds__(256, 2) mma_gemm_aff(
    const float* __restrict__ A, const float* __restrict__ BT, float* __restrict__ C,
    int K, int lda, int ldb, int ldc,
    const float* __restrict__ bias, const float* __restrict__ resid, int ldr,
    const float* __restrict__ affA, const float* __restrict__ affC, float* stats)
{
    extern __shared__ float smem[];
    float* sAf = smem + 2*BUF_W;
    float* sCf = sAf + 256;
    int tid = threadIdx.x, lane = tid & 31, warp = tid >> 5;
    if (tid < 256) { sAf[tid] = affA[tid]; sCf[tid] = affC[tid]; }
    int wm = warp & 1, wn = warp >> 1;
    int m0 = blockIdx.y*128, n0 = blockIdx.x*128;
    float acc[4][4][4];
#pragma unroll
    for (int a2 = 0; a2 < 4; a2++)
#pragma unroll
        for (int b2 = 0; b2 < 4; b2++)
#pragma unroll
            for (int c2 = 0; c2 < 4; c2++) acc[a2][b2][c2] = 0.0f;

    unsigned sbase = (unsigned)__cvta_generic_to_shared(smem);
    unsigned aoff = ((unsigned)((wm*64 + (lane & 15))*TILE_ST) + (lane >= 16 ? 4u : 0u))*4u;
    unsigned boff = (unsigned)TILE_W*4u +
                    ((unsigned)((wn*32 + (lane & 7) + ((lane >> 4) << 3))*TILE_ST) +
                     ((lane >> 3) & 1)*4u)*4u;

    int nk = K >> 5;
    load_tile128(smem, smem + TILE_W, A, BT, lda, ldb, m0, n0, 0, tid);

    for (int it = 0; it < nk; it++) {
        asm volatile("cp.async.wait_group 0;");
        __syncthreads();
        int cur = it & 1;
        if (it + 1 < nk)
            load_tile128(smem + (cur^1)*BUF_W, smem + (cur^1)*BUF_W + TILE_W,
                      A, BT, lda, ldb, m0, n0, (it+1)*32, tid);
        unsigned ubuf = sbase + (unsigned)cur*BUF_W*4u;
#pragma unroll
        for (int kk = 0; kk < 4; kk++) {
            unsigned kbb = (unsigned)(kk*8)*4u;
            int kg = it*32 + kk*8 + (lane & 3);
            float a0 = sAf[kg], a1 = sAf[kg + 4];
            unsigned af[4][4], bf[4][2];
#pragma unroll
            for (int mt = 0; mt < 4; mt++) {
                unsigned addr = ubuf + aoff + (unsigned)(mt*16*TILE_ST)*4u + kbb;
                asm volatile("ldmatrix.sync.aligned.m8n8.x4.shared.b16 {%0,%1,%2,%3}, [%4];"
                    : "=r"(af[mt][0]), "=r"(af[mt][1]), "=r"(af[mt][2]), "=r"(af[mt][3])
                    : "r"(addr));
                af[mt][0] = f2tf(a0*__uint_as_float(af[mt][0]));
                af[mt][1] = f2tf(a0*__uint_as_float(af[mt][1]));
                af[mt][2] = f2tf(a1*__uint_as_float(af[mt][2]));
                af[mt][3] = f2tf(a1*__uint_as_float(af[mt][3]));
            }
#pragma unroll
            for (int p = 0; p < 2; p++) {
                unsigned addr = ubuf + boff + (unsigned)(p*16*TILE_ST)*4u + kbb;
                asm volatile("ldmatrix.sync.aligned.m8n8.x4.shared.b16 {%0,%1,%2,%3}, [%4];"
                    : "=r"(bf[2*p][0]), "=r"(bf[2*p][1]), "=r"(bf[2*p+1][0]), "=r"(bf[2*p+1][1])
                    : "r"(addr));
            }
#pragma unroll
            for (int mt = 0; mt < 4; mt++)
#pragma unroll
                for (int nt = 0; nt < 4; nt++)
                    asm volatile(
                        "mma.sync.aligned.m16n8k8.row.col.f32.tf32.tf32.f32 "
                        "{%0,%1,%2,%3}, {%4,%5,%6,%7}, {%8,%9}, {%0,%1,%2,%3};"
                        : "+f"(acc[mt][nt][0]), "+f"(acc[mt][nt][1]),
                          "+f"(acc[mt][nt][2]), "+f"(acc[mt][nt][3])
                        : "r"(af[mt][0]), "r"(af[mt][1]), "r"(af[mt][2]), "r"(af[mt][3]),
                          "r"(bf[nt][0]), "r"(bf[nt][1]));
        }
    }
    float cs[4][2] = {}, cs2[4][2] = {};
#pragma unroll
    for (int mt = 0; mt < 4; mt++) {
#pragma unroll
        for (int nt = 0; nt < 4; nt++) {
            int r = m0 + wm*64 + mt*16 + (lane >> 2);
            int c = n0 + wn*32 + nt*8 + (lane & 3)*2;
            float ac0 = sAf[c], cc0 = sCf[c], ac1 = sAf[c+1], cc1 = sCf[c+1];
#pragma unroll
            for (int half = 0; half < 2; half++) {
                int rr = r + half*8;
                float v0 = acc[mt][nt][half*2+0] + bias[c];
                float v1 = acc[mt][nt][half*2+1] + bias[c+1];
                v0 = fmaxf(v0, 0.0f); v1 = fmaxf(v1, 0.0f);
                float2 rv = *(const float2*)&resid[(size_t)rr*ldr + c];
                v0 += ac0*rv.x + cc0;
                v1 += ac1*rv.y + cc1;
                *(float2*)&C[(size_t)rr*ldc + c] = make_float2(v0, v1);
                cs[nt][0]  += v0;    cs[nt][1]  += v1;
                cs2[nt][0] += v0*v0; cs2[nt][1] += v1*v1;
            }
        }
    }
    {
        float* red = smem;
        __syncthreads();
        if (tid < 256) red[tid] = 0.0f;
        __syncthreads();
#pragma unroll
        for (int nt = 0; nt < 4; nt++) {
#pragma unroll
            for (int j = 0; j < 2; j++) {
                float s = cs[nt][j], s2 = cs2[nt][j];
#pragma unroll
                for (int o = 16; o >= 4; o >>= 1) {
                    s  += __shfl_xor_sync(0xffffffffu, s,  o);
                    s2 += __shfl_xor_sync(0xffffffffu, s2, o);
                }
                if ((lane >> 2) == 0) {
                    int cc = wn*32 + nt*8 + (lane & 3)*2 + j;
                    atomicAdd(&red[cc], s);
                    atomicAdd(&red[128 + cc], s2);
                }
            }
        }
        __syncthreads();
        if (tid < 128) {
            atomicAdd(&stats[n0 + tid],      red[tid]);
            atomicAdd(&stats[EE + n0 + tid], red[128 + tid]);
        }
    }
}

// ---- per-layer BN1 absorption prep: a[k], c[k], bias2[n] = bff[n] + sum_k c[k]W[n][k]
__global__ void bn_prep(const float* __restrict__ sums,
                        const float* __restrict__ g1, const float* __restrict__ b1,
                        const float* __restrict__ wffT_l, const float* __restrict__ bff_l)
{
    __shared__ float wsum[4];
    int n = blockIdx.x, j = threadIdx.x;   // 256 blocks x 128 threads
    const float invN = 1.0f/(float)TT;
    float partial = 0.0f;
    for (int k = j; k < EE; k += 128) {
        float mean = sums[k]*invN;
        float var  = sums[EE + k]*invN - mean*mean;
        float rstd = rsqrtf(var + 1e-5f);
        float a = g1[k]*rstd;
        float c = b1[k] - g1[k]*mean*rstd;
        if (n == 0) { g_bnA[k] = a; g_bnC[k] = c; }
        partial += c * wffT_l[(size_t)n*EE + k];
    }
#pragma unroll
    for (int o = 16; o > 0; o >>= 1) partial += __shfl_down_sync(0xffffffffu, partial, o);
    if ((j & 31) == 0) wsum[j >> 5] = partial;
    __syncthreads();
    if (j == 0) g_bias2[n] = bff_l[n] + wsum[0] + wsum[1] + wsum[2] + wsum[3];
}

__device__ __forceinline__ bool adj_fn(int g, int q, int k, int len, const int* fl) {
    if (q == k) return q < len;
    if (g == 0) {
        if (k == q+1) return fl[q] == 100 && q < len-1;
        if (q == k+1) return fl[k] == 100 && k < len-1;
        return false;
    } else if (g == 1) {
        if (k == q+1) return fl[q] == 100 && q < len-1;
        if (q == k+1) return fl[k] == 100 && k < len-1;
        if (k == q+2) return fl[q] == 100 && fl[q+1] == 100 && q < len-2;
        if (q == k+2) return fl[k] == 100 && fl[k+1] == 100 && k < len-2;
        return false;
    } else {
        if (q == 0 && k == len-1 && len > 1) return true;
        if (k == 0 && q == len-1 && len > 1) return true;
        if (k == q+1) return fl[q] == 101 && q < len-1;
        if (q == k+1) return fl[k] == 101 && k < len-1;
        return false;
    }
}

__global__ void __launch_bounds__(256) attn_kernel(
    const float* __restrict__ qkv, float* __restrict__ xh)
{
    __shared__ float sPart[8][32];
    __shared__ float sVmean[32];
    __shared__ int   sFlag[SS];
    __shared__ int   sLenS;
    int b = blockIdx.x, h = blockIdx.y, g = blockIdx.z;
    int tid = threadIdx.x;
    if (b == 0 && h == 0 && g == 0) {
        g_sums[tid] = 0.0f; g_sums[256+tid] = 0.0f;
        g_sums[512+tid] = 0.0f; g_sums[768+tid] = 0.0f;
    }
    const float* basep = qkv + (size_t)b*SS*QKVW + g*768 + h*DKK;
    {
        int d = tid & 31, ch = tid >> 5;
        float s = 0.0f;
        for (int r = ch*32; r < ch*32 + 32; r++)
            s += basep[(size_t)r*QKVW + 512 + d];
        sPart[ch][d] = s;
    }
    sFlag[tid] = g_flag[b*SS + tid];
    if (tid == 0) sLenS = g_len[b];
    __syncthreads();
    if (tid < 32) {
        float s = 0.0f;
#pragma unroll
        for (int c2 = 0; c2 < 8; c2++) s += sPart[c2][tid];
        sVmean[tid] = rtf(s * (1.0f/256.0f));
    }
    __syncthreads();
    int qi = tid, len = sLenS;
    float* op = xh + (size_t)(b*SS + qi)*XHW + 256 + g*256 + h*DKK;
    if (qi >= len) {
#pragma unroll
        for (int j = 0; j < 8; j++)
            *(float4*)(op + j*4) = *(float4*)(&sVmean[j*4]);
        return;
    }
    float qr[32];
    const float* qp = basep + (size_t)qi*QKVW;
#pragma unroll
    for (int j = 0; j < 8; j++) {
        float4 t4 = *(const float4*)(qp + j*4);
        qr[j*4+0] = t4.x; qr[j*4+1] = t4.y; qr[j*4+2] = t4.z; qr[j*4+3] = t4.w;
    }
    int cand[8]; int nc = 0;
    int pot[7];  int np = 0;
    if (g == 2) pot[np++] = 0;
    pot[np++] = qi-2; pot[np++] = qi-1; pot[np++] = qi; pot[np++] = qi+1; pot[np++] = qi+2;
    if (g == 2) pot[np++] = len-1;
    for (int i = 0; i < np; i++) {
        int kk = pot[i];
        if (kk < 0 || kk >= SS) continue;
        if (!adj_fn(g, qi, kk, len, sFlag)) continue;
        bool dup = false;
        for (int u = 0; u < nc; u++) if (cand[u] == kk) dup = true;
        if (!dup) cand[nc++] = kk;
    }
    const float scale = 0.17677669529663687f;
    float lg[8];
    float m = -1e30f;
    for (int i = 0; i < nc; i++) {
        const float* kp = basep + (size_t)cand[i]*QKVW + 256;
        float dot = 0.0f;
#pragma unroll
        for (int j = 0; j < 8; j++) {
            float4 k4 = *(const float4*)(kp + j*4);
            dot += qr[j*4+0]*k4.x + qr[j*4+1]*k4.y + qr[j*4+2]*k4.z + qr[j*4+3]*k4.w;
        }
        lg[i] = dot * scale;
        m = fmaxf(m, lg[i]);
    }
    float ssum = 0.0f;
    float o[32];
#pragma unroll
    for (int d = 0; d < 32; d++) o[d] = 0.0f;
    for (int i = 0; i < nc; i++) {
        float p = __expf(lg[i] - m);
        ssum += p;
        const float* vp = basep + (size_t)cand[i]*QKVW + 512;
#pragma unroll
        for (int j = 0; j < 8; j++) {
            float4 v4 = *(const float4*)(vp + j*4);
            o[j*4+0] += p*v4.x; o[j*4+1] += p*v4.y; o[j*4+2] += p*v4.z; o[j*4+3] += p*v4.w;
        }
    }
    float inv = 1.0f / ssum;
#pragma unroll
    for (int j = 0; j < 8; j++) {
        float4 w4 = make_float4(rtf(o[j*4+0]*inv), rtf(o[j*4+1]*inv),
                                rtf(o[j*4+2]*inv), rtf(o[j*4+3]*inv));
        *(float4*)(op + j*4) = w4;
    }
}

__global__ void __launch_bounds__(256) bn_norm_kernel(
    const float* __restrict__ in, float* __restrict__ outp,
    const float* __restrict__ gamma, const float* __restrict__ beta,
    const float* __restrict__ sums, int out_ld)
{
    int tid = threadIdx.x;
    int f = (tid & 63)*4;
    int t = blockIdx.x*4 + (tid >> 6);
    float4 s  = *(const float4*)&sums[f];
    float4 s2 = *(const float4*)&sums[EE + f];
    const float invN = 1.0f/(float)TT;
    float m0 = s.x*invN, m1 = s.y*invN, m2 = s.z*invN, m3 = s.w*invN;
    float r0 = rsqrtf(s2.x*invN - m0*m0 + 1e-5f);
    float r1 = rsqrtf(s2.y*invN - m1*m1 + 1e-5f);
    float r2 = rsqrtf(s2.z*invN - m2*m2 + 1e-5f);
    float r3 = rsqrtf(s2.w*invN - m3*m3 + 1e-5f);
    float4 v  = *(const float4*)&in[(size_t)t*EE + f];
    float4 gm = *(const float4*)&gamma[f];
    float4 bt = *(const float4*)&beta[f];
    float4 o;
    o.x = rtf(gm.x*(v.x - m0)*r0 + bt.x);
    o.y = rtf(gm.y*(v.y - m1)*r1 + bt.y);
    o.z = rtf(gm.z*(v.z - m2)*r2 + bt.z);
    o.w = rtf(gm.w*(v.w - m3)*r3 + bt.w);
    *(float4*)&outp[(size_t)t*out_ld + f] = o;
}

__global__ void final_kernel(const float* __restrict__ mask, float* __restrict__ outp) {
    __shared__ float sM[SS];
    int b = blockIdx.x, e = threadIdx.x;
    sM[e] = mask[b*SS + e];
    __syncthreads();
    float acc = 0.0f;
    for (int s = 0; s < SS; s++) acc += g_xh[(size_t)(b*SS + s)*XHW + e]*sM[s];
    float denom = fmaxf((float)g_len[b], 1.0f);
    outp[b*EE + e] = acc/denom;
}

extern "C" void kernel_launch(void* const* d_in, const int* in_sizes, int n_in,
                              void* d_out, int out_size) {
    (void)in_sizes; (void)n_in; (void)out_size;
    const float* data = (const float*)d_in[0];
    const float* mask = (const float*)d_in[1];
    const float* Wc   = (const float*)d_in[2];
    const float* bc   = (const float*)d_in[3];
    const float* ftab = (const float*)d_in[4];
    const float* ptab = (const float*)d_in[5];
    const float* Wq   = (const float*)d_in[6];
    const float* Wk   = (const float*)d_in[7];
    const float* Wv   = (const float*)d_in[8];
    const float* Wo   = (const float*)d_in[9];
    const float* Wf   = (const float*)d_in[10];
    const float* bf   = (const float*)d_in[11];
    const float* g1   = (const float*)d_in[12];
    const float* b1   = (const float*)d_in[13];
    const float* Wff  = (const float*)d_in[14];
    const float* bff  = (const float*)d_in[15];
    const float* g2   = (const float*)d_in[16];
    const float* b2   = (const float*)d_in[17];
    float* outp = (float*)d_out;

    float *xh, *qkv, *h, *h2, *wqkvT, *wfT, *wffT, *woR, *wcomb, *wbigT, *sums, *bnA, *bnC, *bias2;
    cudaGetSymbolAddress((void**)&xh,    g_xh);
    cudaGetSymbolAddress((void**)&qkv,   g_qkv);
    cudaGetSymbolAddress((void**)&h,     g_h);
    cudaGetSymbolAddress((void**)&h2,    g_h2);
    cudaGetSymbolAddress((void**)&wqkvT, g_wqkvT);
    cudaGetSymbolAddress((void**)&wfT,   g_wfT);
    cudaGetSymbolAddress((void**)&wffT,  g_wffT);
    cudaGetSymbolAddress((void**)&woR,   g_woR);
    cudaGetSymbolAddress((void**)&wcomb, g_wcomb);
    cudaGetSymbolAddress((void**)&wbigT, g_wbigT);
    cudaGetSymbolAddress((void**)&sums,  g_sums);
    cudaGetSymbolAddress((void**)&bnA,   g_bnA);
    cudaGetSymbolAddress((void**)&bnC,   g_bnC);
    cudaGetSymbolAddress((void**)&bias2, g_bias2);

    cudaFuncSetAttribute(mma_gemm,     cudaFuncAttributeMaxDynamicSharedMemorySize, GEMM_SMEM);
    cudaFuncSetAttribute(mma_gemm_aff, cudaFuncAttributeMaxDynamicSharedMemorySize, GEMM_AFF_SMEM);

    prep_w<<<(3*N_PACK + LL*EE*EE)/256, 256>>>(Wq, Wk, Wv, Wo, Wf, Wff);
    mma_gemm<<<dim3(2, 2, 12), 256, GEMM_SMEM>>>(
        woR, wfT, wcomb, EE, EE, EE, EE, nullptr, nullptr, 0, 0,
        (size_t)EE*EE, (size_t)EE*EE, (size_t)EE*EE, nullptr);
    assemble_wbigT<<<(LL*EE*XHW)/256, 256>>>(Wf);

    flags_kernel<<<BB, SS>>>(data, mask);
    embed_kernel<<<TT, EE>>>(data, Wc, bc, ftab, ptab);

    for (int l = 0; l < LL; l++) {
        mma_gemm<<<dim3(QKVW/128, TT/128, 1), 256, GEMM_SMEM>>>(
            xh, wqkvT + (size_t)l*QKVW*EE, qkv,
            EE, XHW, EE, QKVW, nullptr, nullptr, 0, 0, 0, 0, 0, nullptr);
        attn_kernel<<<dim3(BB, HH, 3), 256>>>(qkv, xh);
        mma_gemm<<<dim3(EE/128, TT/128, 1), 256, GEMM_SMEM>>>(
            xh, wbigT + (size_t)l*EE*XHW, h,
            XHW, XHW, XHW, EE, bf + l*EE, nullptr, 0, 0, 0, 0, 0, sums);
        bn_prep<<<EE, 128>>>(sums, g1 + l*EE, b1 + l*EE,
                             wffT + (size_t)l*EE*EE, bff + l*EE);
        mma_gemm_aff<<<dim3(EE/128, TT/128, 1), 256, GEMM_AFF_SMEM>>>(
            h, wffT + (size_t)l*EE*EE, h2,
            EE, EE, EE, EE, bias2, h, EE, bnA, bnC, sums + 2*EE);
        bn_norm_kernel<<<TT/4, 256>>>(h2, xh, g2 + l*EE, b2 + l*EE, sums + 2*EE, XHW);
    }
    final_kernel<<<BB, EE>>>(mask, outp);
}